// round 13
// baseline (speedup 1.0000x reference)
#include <cuda_runtime.h>
#include <cuda_fp16.h>
#include <cstdint>

#define NN 100000
#define NE 1600000
#define CSRB 98          // 98 * 1024 = 100352 >= NN; all CTAs co-resident

// ---------------- scratch (device globals; no allocation allowed) -------------
__device__ __half g_z1h[(size_t)NN * 128]; // x@W1l (aggregated half)  fp16
__device__ float  g_z1r[(size_t)NN * 128]; // x@W1r (root half)        fp32
__device__ float  g_h  [(size_t)NN * 128]; // relu(layer1)
__device__ __half g_z2h[(size_t)NN * 64];  // h@W2l                    fp16
__device__ float  g_z2r[(size_t)NN * 64];  // h@W2r                    fp32
__device__ __half g_w1f[256 * 128];        // W1 concat, transposed [h',d] fp16
__device__ __half g_w2f[128 * 128];        // W2 concat, transposed [o',k] fp16
__device__ int   g_deg[NN];
__device__ int   g_rowptr[NN];
__device__ int   g_pos[NN];
__device__ int   g_csr[NE];
__device__ int   g_sagg[128];
__device__ int   g_bar[4];

// ---------------- helpers ------------------------------------------------------
__device__ __forceinline__ uint32_t smem_u32(const void* p) {
    uint32_t a;
    asm("{ .reg .u64 t; cvta.to.shared.u64 t, %1; cvt.u32.u64 %0, t; }" : "=r"(a) : "l"(p));
    return a;
}
#define LDSM_X4(r0, r1, r2, r3, a) \
    asm volatile("ldmatrix.sync.aligned.m8n8.x4.shared.b16 {%0,%1,%2,%3}, [%4];" \
        : "=r"(r0), "=r"(r1), "=r"(r2), "=r"(r3) : "r"(a))
#define MMA16816F(c, a, b0, b1) \
    asm volatile("mma.sync.aligned.m16n8k16.row.col.f32.f16.f16.f32 " \
        "{%0,%1,%2,%3}, {%4,%5,%6,%7}, {%8,%9}, {%0,%1,%2,%3};" \
        : "+f"((c)[0]), "+f"((c)[1]), "+f"((c)[2]), "+f"((c)[3]) \
        : "r"((a)[0]), "r"((a)[1]), "r"((a)[2]), "r"((a)[3]), "r"(b0), "r"(b1))

// grid-wide barrier: all CSRB blocks co-resident (98 <= 148 SMs) -> safe spin
__device__ __forceinline__ void gbar(int idx) {
    __threadfence();                 // every thread: flush my writes to L2
    __syncthreads();
    if (threadIdx.x == 0) {
        atomicAdd(&g_bar[idx], 1);
        while (atomicAdd(&g_bar[idx], 0) < CSRB) {}
    }
    __syncthreads();
}

// ---------------- fused init: weight prep (fp16) + zero deg + zero barriers ---
__global__ void k_init(const float* __restrict__ W1l, const float* __restrict__ W1r,
                       const float* __restrict__ W2l, const float* __restrict__ W2r) {
    int i = blockIdx.x * 256 + threadIdx.x;
    if (i < 256 * 128) {                        // w1: i = hp*128 + d
        int hp = i >> 7, d = i & 127;
        float v = (hp < 128) ? W1l[d * 128 + hp] : W1r[d * 128 + (hp - 128)];
        g_w1f[i] = __float2half(v);
    }
    if (i < 128 * 128) {                        // w2: i = op*128 + k
        int op = i >> 7, k = i & 127;
        float v = (op < 64) ? W2l[k * 64 + op] : W2r[k * 64 + (op - 64)];
        g_w2f[i] = __float2half(v);
    }
    if (i < NN) g_deg[i] = 0;
    if (i < 4) g_bar[i] = 0;
}

// ---------------- fused CSR build: hist + scan + fill, one persistent kernel --
__global__ __launch_bounds__(1024, 1) void k_csr(const int* __restrict__ src,
                                                 const int* __restrict__ dst) {
    __shared__ int sm[1024];
    __shared__ int s_off;
    int t = threadIdx.x, b = blockIdx.x;

    // phase A: degree histogram
    for (int e = b * 1024 + t; e < NE; e += CSRB * 1024)
        atomicAdd(&g_deg[dst[e]], 1);
    gbar(0);

    // phase B: exclusive scan of degrees
    int i = b * 1024 + t;
    int v = (i < NN) ? __ldcg(&g_deg[i]) : 0;
    sm[t] = v;
    __syncthreads();
    for (int off = 1; off < 1024; off <<= 1) {
        int tmp = (t >= off) ? sm[t - off] : 0;
        __syncthreads();
        sm[t] += tmp;
        __syncthreads();
    }
    int incl = sm[t];
    if (t == 1023) g_sagg[b] = sm[1023];
    gbar(1);
    if (t < 32) {                               // block-offset = sum of predecessors
        int sum = 0;
        for (int j = t; j < b; j += 32) sum += __ldcg(&g_sagg[j]);
#pragma unroll
        for (int o = 16; o; o >>= 1) sum += __shfl_xor_sync(0xffffffffu, sum, o);
        if (t == 0) s_off = sum;
    }
    __syncthreads();
    if (i < NN) {
        int val = incl - v + s_off;             // exclusive prefix
        g_rowptr[i] = val;
        g_pos[i]    = val;
    }
    gbar(2);

    // phase C: scatter fill (src grouped by dst)
    for (int e = b * 1024 + t; e < NE; e += CSRB * 1024) {
        int idx = atomicAdd(&g_pos[dst[e]], 1);
        g_csr[idx] = src[e];
    }
}

// ---------------- mma.sync single-pass fp16 GEMM ------------------------------
// A[M x 128] fp32 -> fp16; B [Ntot x 128] fp16 K-major. C cols < split -> fp16
// buffer Ch, cols >= split -> fp32 buffer Cf. split multiple of 32.
#define SPAD   136
#define SMATB  (128 * SPAD * 2)        // 34816 B per matrix
#define SMEM_TOT (2 * SMATB)           // 69632 B -> 2 CTAs/SM

__global__ __launch_bounds__(256, 2) void k_gemm_mma(
    const float* __restrict__ A, int M,
    __half* __restrict__ Ch, int ldh,
    float* __restrict__ Cf, int ldf, int split,
    const __half* __restrict__ Bf)
{
    extern __shared__ __align__(16) char smem[];
    uint32_t s0 = smem_u32(smem);
    const uint32_t sa = s0, sb = s0 + SMATB;

    int tid = threadIdx.x, lane = tid & 31, wid = tid >> 5;
    int row = tid >> 1, half = tid & 1;

    // --- A tile: fp32 -> fp16 -> padded smem ---
    {
        int gRow = blockIdx.y * 128 + row;
        bool valid = gRow < M;
        const float4* Ar = (const float4*)(A + (size_t)gRow * 128 + half * 64);
        uint32_t base = (uint32_t)(row * SPAD + half * 64) * 2;
#pragma unroll
        for (int j = 0; j < 8; j++) {
            float4 v0 = make_float4(0.f, 0.f, 0.f, 0.f), v1 = v0;
            if (valid) { v0 = Ar[j * 2]; v1 = Ar[j * 2 + 1]; }
            __half2 h0 = __floats2half2_rn(v0.x, v0.y);
            __half2 h1 = __floats2half2_rn(v0.z, v0.w);
            __half2 h2 = __floats2half2_rn(v1.x, v1.y);
            __half2 h3 = __floats2half2_rn(v1.z, v1.w);
            asm volatile("st.shared.v4.b32 [%0], {%1,%2,%3,%4};" :: "r"(sa + base + j * 16),
                "r"(*(uint32_t*)&h0), "r"(*(uint32_t*)&h1),
                "r"(*(uint32_t*)&h2), "r"(*(uint32_t*)&h3) : "memory");
        }
    }
    // --- B tile: fp16 from global -> padded smem ---
    {
        size_t nRow = (size_t)(blockIdx.x * 128 + row);
        const uint4* Br = (const uint4*)(Bf + nRow * 128 + half * 64);
        uint32_t base = (uint32_t)(row * SPAD + half * 64) * 2;
#pragma unroll
        for (int j = 0; j < 8; j++) {
            uint4 bv = Br[j];
            asm volatile("st.shared.v4.b32 [%0], {%1,%2,%3,%4};" :: "r"(sb + base + j * 16),
                "r"(bv.x), "r"(bv.y), "r"(bv.z), "r"(bv.w) : "memory");
        }
    }
    __syncthreads();

    // --- warp grid 2(M) x 4(N): warp tile 64 x 32 ---
    int wm = (wid >> 2) * 64, wn = (wid & 3) * 32;
    float acc[4][4][4];
#pragma unroll
    for (int i = 0; i < 4; i++)
#pragma unroll
        for (int j = 0; j < 4; j++)
#pragma unroll
            for (int q = 0; q < 4; q++) acc[i][j][q] = 0.f;

    uint32_t aRow = (uint32_t)(wm + (lane & 15));
    uint32_t aKof = (uint32_t)((lane >> 4) * 8);
    uint32_t bRow = (uint32_t)(wn + (lane & 7) + ((lane >> 4) << 3));
    uint32_t bKof = (uint32_t)(((lane >> 3) & 1) * 8);

#pragma unroll
    for (int ks = 0; ks < 8; ks++) {
        int k0 = ks * 16;
        uint32_t ah[4][4], bh[2][4];
#pragma unroll
        for (int mi = 0; mi < 4; mi++) {
            uint32_t a = (uint32_t)((aRow + mi * 16) * SPAD + k0 + aKof) * 2;
            LDSM_X4(ah[mi][0], ah[mi][1], ah[mi][2], ah[mi][3], sa + a);
        }
#pragma unroll
        for (int nb = 0; nb < 2; nb++) {
            uint32_t a = (uint32_t)((bRow + nb * 16) * SPAD + k0 + bKof) * 2;
            LDSM_X4(bh[nb][0], bh[nb][1], bh[nb][2], bh[nb][3], sb + a);
        }
#pragma unroll
        for (int mi = 0; mi < 4; mi++)
#pragma unroll
            for (int nj = 0; nj < 4; nj++) {
                int nb = nj >> 1, bo = (nj & 1) * 2;
                MMA16816F(acc[mi][nj], ah[mi], bh[nb][bo], bh[nb][bo + 1]);
            }
    }

    // --- epilogue: left cols -> fp16, right cols -> fp32 ---
    int gcolw = blockIdx.x * 128 + wn;
    bool leftw = gcolw < split;
    int crow0 = blockIdx.y * 128 + wm + (lane >> 2);
    int ccol0 = gcolw + (lane & 3) * 2;
#pragma unroll
    for (int mi = 0; mi < 4; mi++) {
#pragma unroll
        for (int nj = 0; nj < 4; nj++) {
            int r0 = crow0 + mi * 16;
            int cc = ccol0 + nj * 8;
            if (leftw) {
                __half2 v01 = __floats2half2_rn(acc[mi][nj][0], acc[mi][nj][1]);
                __half2 v23 = __floats2half2_rn(acc[mi][nj][2], acc[mi][nj][3]);
                if (r0 < M)     *(__half2*)(Ch + (size_t)r0 * ldh + cc) = v01;
                if (r0 + 8 < M) *(__half2*)(Ch + (size_t)(r0 + 8) * ldh + cc) = v23;
            } else {
                int cf = cc - split;
                if (r0 < M)
                    *(float2*)(Cf + (size_t)r0 * ldf + cf) = make_float2(acc[mi][nj][0], acc[mi][nj][1]);
                if (r0 + 8 < M)
                    *(float2*)(Cf + (size_t)(r0 + 8) * ldf + cf) = make_float2(acc[mi][nj][2], acc[mi][nj][3]);
            }
        }
    }
}

// ---------------- pull-mode mean aggregation (fp16 gather) --------------------
__global__ void k_agg1(const float* __restrict__ b1) {
    int gt = blockIdx.x * blockDim.x + threadIdx.x;
    int w = gt >> 5, lane = gt & 31;
    if (w >= NN) return;
    int start = g_rowptr[w], deg = g_deg[w];
    float4 acc = make_float4(0.f, 0.f, 0.f, 0.f);
    for (int e = 0; e < deg; e++) {
        int s = g_csr[start + e];
        uint2 u = *(const uint2*)(g_z1h + (size_t)s * 128 + lane * 4);
        float2 a = __half22float2(*(__half2*)&u.x);
        float2 b = __half22float2(*(__half2*)&u.y);
        acc.x += a.x; acc.y += a.y; acc.z += b.x; acc.w += b.y;
    }
    float inv = 1.f / (float)(deg > 0 ? deg : 1);
    float4 r  = *(const float4*)(g_z1r + (size_t)w * 128 + lane * 4);
    float4 bb = *(const float4*)(b1 + lane * 4);
    float4 o;
    o.x = fmaxf(fmaf(acc.x, inv, bb.x + r.x), 0.f);
    o.y = fmaxf(fmaf(acc.y, inv, bb.y + r.y), 0.f);
    o.z = fmaxf(fmaf(acc.z, inv, bb.z + r.z), 0.f);
    o.w = fmaxf(fmaf(acc.w, inv, bb.w + r.w), 0.f);
    *(float4*)(g_h + (size_t)w * 128 + lane * 4) = o;
}

__global__ void k_agg2(const float* __restrict__ b2, float* __restrict__ out) {
    int gt = blockIdx.x * blockDim.x + threadIdx.x;
    int w = gt >> 5, lane = gt & 31;
    if (w >= NN) return;
    int start = g_rowptr[w], deg = g_deg[w];
    float2 acc = make_float2(0.f, 0.f);
    for (int e = 0; e < deg; e++) {
        int s = g_csr[start + e];
        uint32_t u = *(const uint32_t*)(g_z2h + (size_t)s * 64 + lane * 2);
        float2 a = __half22float2(*(__half2*)&u);
        acc.x += a.x; acc.y += a.y;
    }
    float inv = 1.f / (float)(deg > 0 ? deg : 1);
    float2 r = *(const float2*)(g_z2r + (size_t)w * 64 + lane * 2);
    float2 o;
    o.x = fmaf(acc.x, inv, b2[lane * 2 + 0] + r.x);
    o.y = fmaf(acc.y, inv, b2[lane * 2 + 1] + r.y);
    *(float2*)(out + (size_t)w * 64 + lane * 2) = o;
}

// ---------------- launch ------------------------------------------------------
extern "C" void kernel_launch(void* const* d_in, const int* in_sizes, int n_in,
                              void* d_out, int out_size)
{
    const float* x   = (const float*)d_in[0];
    const int*   ei  = (const int*)d_in[1];
    const float* W1l = (const float*)d_in[2];
    const float* b1  = (const float*)d_in[3];
    const float* W1r = (const float*)d_in[4];
    const float* W2l = (const float*)d_in[5];
    const float* b2  = (const float*)d_in[6];
    const float* W2r = (const float*)d_in[7];
    float* out = (float*)d_out;
    const int* src = ei;
    const int* dst = ei + NE;

    float *z1r, *h, *z2r;
    __half *z1h, *z2h, *w1f, *w2f;
    cudaGetSymbolAddress((void**)&z1h, g_z1h);
    cudaGetSymbolAddress((void**)&z1r, g_z1r);
    cudaGetSymbolAddress((void**)&h,   g_h);
    cudaGetSymbolAddress((void**)&z2h, g_z2h);
    cudaGetSymbolAddress((void**)&z2r, g_z2r);
    cudaGetSymbolAddress((void**)&w1f, g_w1f);
    cudaGetSymbolAddress((void**)&w2f, g_w2f);

    cudaFuncSetAttribute(k_gemm_mma, cudaFuncAttributeMaxDynamicSharedMemorySize, SMEM_TOT);

    // launch order (harness has 2 pre-launches; ncu -s 5 captures OUR idx 3 = k_agg1):
    // 0 init, 1 csr, 2 gemm1, 3 agg1, 4 gemm2, 5 agg2
    k_init<<<(NN + 255) / 256, 256>>>(W1l, W1r, W2l, W2r);
    k_csr<<<CSRB, 1024>>>(src, dst);

    int mtiles = (NN + 127) / 128;

    k_gemm_mma<<<dim3(2, mtiles), 256, SMEM_TOT>>>(x, NN, z1h, 128, z1r, 128, 128, w1f);
    k_agg1<<<(NN * 32 + 255) / 256, 256>>>(b1);

    k_gemm_mma<<<dim3(1, mtiles), 256, SMEM_TOT>>>(h, NN, z2h, 64, z2r, 64, 64, w2f);
    k_agg2<<<(NN * 32 + 255) / 256, 256>>>(b2, out);
}

// round 16
// speedup vs baseline: 1.0619x; 1.0619x over previous
#include <cuda_runtime.h>
#include <cuda_fp16.h>
#include <cstdint>

#define NN 100000
#define NE 1600000

// ---------------- scratch (device globals; no allocation allowed) -------------
__device__ __half g_z1h[(size_t)NN * 128]; // x@W1l (aggregated half)  fp16
__device__ float  g_z1r[(size_t)NN * 128]; // x@W1r (root half)        fp32
__device__ float  g_h  [(size_t)NN * 128]; // relu(layer1)
__device__ __half g_z2h[(size_t)NN * 64];  // h@W2l                    fp16
__device__ float  g_z2r[(size_t)NN * 64];  // h@W2r                    fp32
__device__ __half g_w1f[256 * 128];        // W1 concat, transposed [h',d] fp16
__device__ __half g_w2f[128 * 128];        // W2 concat, transposed [o',k] fp16
__device__ int   g_deg[NN];
__device__ int   g_rowptr[NN];
__device__ int   g_pos[NN];
__device__ int   g_csr[NE];
__device__ int   g_sagg[128];
__device__ int   g_sflag[128];

// ---------------- helpers ------------------------------------------------------
__device__ __forceinline__ uint32_t smem_u32(const void* p) {
    uint32_t a;
    asm("{ .reg .u64 t; cvta.to.shared.u64 t, %1; cvt.u32.u64 %0, t; }" : "=r"(a) : "l"(p));
    return a;
}
#define LDSM_X4(r0, r1, r2, r3, a) \
    asm volatile("ldmatrix.sync.aligned.m8n8.x4.shared.b16 {%0,%1,%2,%3}, [%4];" \
        : "=r"(r0), "=r"(r1), "=r"(r2), "=r"(r3) : "r"(a))
#define MMA16816F(c, a, b0, b1) \
    asm volatile("mma.sync.aligned.m16n8k16.row.col.f32.f16.f16.f32 " \
        "{%0,%1,%2,%3}, {%4,%5,%6,%7}, {%8,%9}, {%0,%1,%2,%3};" \
        : "+f"((c)[0]), "+f"((c)[1]), "+f"((c)[2]), "+f"((c)[3]) \
        : "r"((a)[0]), "r"((a)[1]), "r"((a)[2]), "r"((a)[3]), "r"(b0), "r"(b1))

// ---------------- fused init: weight prep (fp16) + zero deg + zero flags -------
__global__ void k_init(const float* __restrict__ W1l, const float* __restrict__ W1r,
                       const float* __restrict__ W2l, const float* __restrict__ W2r) {
    int i = blockIdx.x * 256 + threadIdx.x;
    if (i < 256 * 128) {                        // w1: i = hp*128 + d
        int hp = i >> 7, d = i & 127;
        float v = (hp < 128) ? W1l[d * 128 + hp] : W1r[d * 128 + (hp - 128)];
        g_w1f[i] = __float2half(v);
    }
    if (i < 128 * 128) {                        // w2: i = op*128 + k
        int op = i >> 7, k = i & 127;
        float v = (op < 64) ? W2l[k * 64 + op] : W2r[k * 64 + (op - 64)];
        g_w2f[i] = __float2half(v);
    }
    if (i < NN) g_deg[i] = 0;
    if (i < 128) g_sflag[i] = 0;
}

// ---------------- CSR build (R12 3-kernel form: fastest measured) -------------
__global__ void k_hist(const int* __restrict__ dst) {
    int e = blockIdx.x * 256 + threadIdx.x;
    if (e < NE) atomicAdd(&g_deg[dst[e]], 1);
}

// single-kernel exclusive scan: 98 blocks x 1024, all resident -> safe spin
__global__ void k_scan() {
    __shared__ int sm[1024];
    __shared__ int s_off;
    int t = threadIdx.x, b = blockIdx.x;
    int i = b * 1024 + t;
    int v = (i < NN) ? g_deg[i] : 0;
    sm[t] = v;
    __syncthreads();
    for (int off = 1; off < 1024; off <<= 1) {
        int tmp = (t >= off) ? sm[t - off] : 0;
        __syncthreads();
        sm[t] += tmp;
        __syncthreads();
    }
    int incl = sm[t];
    if (t == 0) {
        g_sagg[b] = sm[1023];
        __threadfence();
        atomicExch(&g_sflag[b], 1);
    }
    if (t < 32) {
        int sum = 0;
        for (int j = t; j < b; j += 32) {
            while (atomicAdd(&g_sflag[j], 0) == 0) {}
            sum += atomicAdd(&g_sagg[j], 0);
        }
#pragma unroll
        for (int o = 16; o; o >>= 1) sum += __shfl_xor_sync(0xffffffffu, sum, o);
        if (t == 0) s_off = sum;
    }
    __syncthreads();
    if (i < NN) {
        int val = incl - v + s_off;
        g_rowptr[i] = val;
        g_pos[i]    = val;
    }
}

__global__ void k_fill(const int* __restrict__ src, const int* __restrict__ dst) {
    int e = blockIdx.x * 256 + threadIdx.x;
    if (e < NE) {
        int idx = atomicAdd(&g_pos[dst[e]], 1);
        g_csr[idx] = src[e];
    }
}

// ---------------- mma.sync single-pass fp16 GEMM ------------------------------
#define SPAD   136
#define SMATB  (128 * SPAD * 2)
#define SMEM_TOT (2 * SMATB)

__global__ __launch_bounds__(256, 2) void k_gemm_mma(
    const float* __restrict__ A, int M,
    __half* __restrict__ Ch, int ldh,
    float* __restrict__ Cf, int ldf, int split,
    const __half* __restrict__ Bf)
{
    extern __shared__ __align__(16) char smem[];
    uint32_t s0 = smem_u32(smem);
    const uint32_t sa = s0, sb = s0 + SMATB;

    int tid = threadIdx.x, lane = tid & 31, wid = tid >> 5;
    int row = tid >> 1, half = tid & 1;

    {
        int gRow = blockIdx.y * 128 + row;
        bool valid = gRow < M;
        const float4* Ar = (const float4*)(A + (size_t)gRow * 128 + half * 64);
        uint32_t base = (uint32_t)(row * SPAD + half * 64) * 2;
#pragma unroll
        for (int j = 0; j < 8; j++) {
            float4 v0 = make_float4(0.f, 0.f, 0.f, 0.f), v1 = v0;
            if (valid) { v0 = Ar[j * 2]; v1 = Ar[j * 2 + 1]; }
            __half2 h0 = __floats2half2_rn(v0.x, v0.y);
            __half2 h1 = __floats2half2_rn(v0.z, v0.w);
            __half2 h2 = __floats2half2_rn(v1.x, v1.y);
            __half2 h3 = __floats2half2_rn(v1.z, v1.w);
            asm volatile("st.shared.v4.b32 [%0], {%1,%2,%3,%4};" :: "r"(sa + base + j * 16),
                "r"(*(uint32_t*)&h0), "r"(*(uint32_t*)&h1),
                "r"(*(uint32_t*)&h2), "r"(*(uint32_t*)&h3) : "memory");
        }
    }
    {
        size_t nRow = (size_t)(blockIdx.x * 128 + row);
        const uint4* Br = (const uint4*)(Bf + nRow * 128 + half * 64);
        uint32_t base = (uint32_t)(row * SPAD + half * 64) * 2;
#pragma unroll
        for (int j = 0; j < 8; j++) {
            uint4 bv = Br[j];
            asm volatile("st.shared.v4.b32 [%0], {%1,%2,%3,%4};" :: "r"(sb + base + j * 16),
                "r"(bv.x), "r"(bv.y), "r"(bv.z), "r"(bv.w) : "memory");
        }
    }
    __syncthreads();

    int wm = (wid >> 2) * 64, wn = (wid & 3) * 32;
    float acc[4][4][4];
#pragma unroll
    for (int i = 0; i < 4; i++)
#pragma unroll
        for (int j = 0; j < 4; j++)
#pragma unroll
            for (int q = 0; q < 4; q++) acc[i][j][q] = 0.f;

    uint32_t aRow = (uint32_t)(wm + (lane & 15));
    uint32_t aKof = (uint32_t)((lane >> 4) * 8);
    uint32_t bRow = (uint32_t)(wn + (lane & 7) + ((lane >> 4) << 3));
    uint32_t bKof = (uint32_t)(((lane >> 3) & 1) * 8);

#pragma unroll
    for (int ks = 0; ks < 8; ks++) {
        int k0 = ks * 16;
        uint32_t ah[4][4], bh[2][4];
#pragma unroll
        for (int mi = 0; mi < 4; mi++) {
            uint32_t a = (uint32_t)((aRow + mi * 16) * SPAD + k0 + aKof) * 2;
            LDSM_X4(ah[mi][0], ah[mi][1], ah[mi][2], ah[mi][3], sa + a);
        }
#pragma unroll
        for (int nb = 0; nb < 2; nb++) {
            uint32_t a = (uint32_t)((bRow + nb * 16) * SPAD + k0 + bKof) * 2;
            LDSM_X4(bh[nb][0], bh[nb][1], bh[nb][2], bh[nb][3], sb + a);
        }
#pragma unroll
        for (int mi = 0; mi < 4; mi++)
#pragma unroll
            for (int nj = 0; nj < 4; nj++) {
                int nb = nj >> 1, bo = (nj & 1) * 2;
                MMA16816F(acc[mi][nj], ah[mi], bh[nb][bo], bh[nb][bo + 1]);
            }
    }

    int gcolw = blockIdx.x * 128 + wn;
    bool leftw = gcolw < split;
    int crow0 = blockIdx.y * 128 + wm + (lane >> 2);
    int ccol0 = gcolw + (lane & 3) * 2;
#pragma unroll
    for (int mi = 0; mi < 4; mi++) {
#pragma unroll
        for (int nj = 0; nj < 4; nj++) {
            int r0 = crow0 + mi * 16;
            int cc = ccol0 + nj * 8;
            if (leftw) {
                __half2 v01 = __floats2half2_rn(acc[mi][nj][0], acc[mi][nj][1]);
                __half2 v23 = __floats2half2_rn(acc[mi][nj][2], acc[mi][nj][3]);
                if (r0 < M)     *(__half2*)(Ch + (size_t)r0 * ldh + cc) = v01;
                if (r0 + 8 < M) *(__half2*)(Ch + (size_t)(r0 + 8) * ldh + cc) = v23;
            } else {
                int cf = cc - split;
                if (r0 < M)
                    *(float2*)(Cf + (size_t)r0 * ldf + cf) = make_float2(acc[mi][nj][0], acc[mi][nj][1]);
                if (r0 + 8 < M)
                    *(float2*)(Cf + (size_t)(r0 + 8) * ldf + cf) = make_float2(acc[mi][nj][2], acc[mi][nj][3]);
            }
        }
    }
}

// ---------------- pull-mode mean aggregation (pairwise HADD2) -----------------
__global__ void k_agg1(const float* __restrict__ b1) {
    int gt = blockIdx.x * blockDim.x + threadIdx.x;
    int w = gt >> 5, lane = gt & 31;
    if (w >= NN) return;
    int start = g_rowptr[w], deg = g_deg[w];
    float4 acc = make_float4(0.f, 0.f, 0.f, 0.f);
    const __half* zb = g_z1h + lane * 4;
    int e = 0;
    for (; e + 2 <= deg; e += 2) {
        int s0 = g_csr[start + e];
        int s1 = g_csr[start + e + 1];
        uint2 u0 = *(const uint2*)(zb + (size_t)s0 * 128);
        uint2 u1 = *(const uint2*)(zb + (size_t)s1 * 128);
        __half2 p0 = __hadd2(*(__half2*)&u0.x, *(__half2*)&u1.x);
        __half2 p1 = __hadd2(*(__half2*)&u0.y, *(__half2*)&u1.y);
        float2 a = __half22float2(p0);
        float2 b = __half22float2(p1);
        acc.x += a.x; acc.y += a.y; acc.z += b.x; acc.w += b.y;
    }
    if (e < deg) {
        int s = g_csr[start + e];
        uint2 u = *(const uint2*)(zb + (size_t)s * 128);
        float2 a = __half22float2(*(__half2*)&u.x);
        float2 b = __half22float2(*(__half2*)&u.y);
        acc.x += a.x; acc.y += a.y; acc.z += b.x; acc.w += b.y;
    }
    float inv = 1.f / (float)(deg > 0 ? deg : 1);
    float4 r  = *(const float4*)(g_z1r + (size_t)w * 128 + lane * 4);
    float4 bb = *(const float4*)(b1 + lane * 4);
    float4 o;
    o.x = fmaxf(fmaf(acc.x, inv, bb.x + r.x), 0.f);
    o.y = fmaxf(fmaf(acc.y, inv, bb.y + r.y), 0.f);
    o.z = fmaxf(fmaf(acc.z, inv, bb.z + r.z), 0.f);
    o.w = fmaxf(fmaf(acc.w, inv, bb.w + r.w), 0.f);
    *(float4*)(g_h + (size_t)w * 128 + lane * 4) = o;
}

__global__ void k_agg2(const float* __restrict__ b2, float* __restrict__ out) {
    int gt = blockIdx.x * blockDim.x + threadIdx.x;
    int w = gt >> 5, lane = gt & 31;
    if (w >= NN) return;
    int start = g_rowptr[w], deg = g_deg[w];
    float2 acc = make_float2(0.f, 0.f);
    const __half* zb = g_z2h + lane * 2;
    int e = 0;
    for (; e + 2 <= deg; e += 2) {
        int s0 = g_csr[start + e];
        int s1 = g_csr[start + e + 1];
        uint32_t u0 = *(const uint32_t*)(zb + (size_t)s0 * 64);
        uint32_t u1 = *(const uint32_t*)(zb + (size_t)s1 * 64);
        __half2 p = __hadd2(*(__half2*)&u0, *(__half2*)&u1);
        float2 a = __half22float2(p);
        acc.x += a.x; acc.y += a.y;
    }
    if (e < deg) {
        int s = g_csr[start + e];
        uint32_t u = *(const uint32_t*)(zb + (size_t)s * 64);
        float2 a = __half22float2(*(__half2*)&u);
        acc.x += a.x; acc.y += a.y;
    }
    float inv = 1.f / (float)(deg > 0 ? deg : 1);
    float2 r = *(const float2*)(g_z2r + (size_t)w * 64 + lane * 2);
    float2 o;
    o.x = fmaf(acc.x, inv, b2[lane * 2 + 0] + r.x);
    o.y = fmaf(acc.y, inv, b2[lane * 2 + 1] + r.y);
    *(float2*)(out + (size_t)w * 64 + lane * 2) = o;
}

// ---------------- launch ------------------------------------------------------
extern "C" void kernel_launch(void* const* d_in, const int* in_sizes, int n_in,
                              void* d_out, int out_size)
{
    const float* x   = (const float*)d_in[0];
    const int*   ei  = (const int*)d_in[1];
    const float* W1l = (const float*)d_in[2];
    const float* b1  = (const float*)d_in[3];
    const float* W1r = (const float*)d_in[4];
    const float* W2l = (const float*)d_in[5];
    const float* b2  = (const float*)d_in[6];
    const float* W2r = (const float*)d_in[7];
    float* out = (float*)d_out;
    const int* src = ei;
    const int* dst = ei + NE;

    float *z1r, *h, *z2r;
    __half *z1h, *z2h, *w1f, *w2f;
    cudaGetSymbolAddress((void**)&z1h, g_z1h);
    cudaGetSymbolAddress((void**)&z1r, g_z1r);
    cudaGetSymbolAddress((void**)&h,   g_h);
    cudaGetSymbolAddress((void**)&z2h, g_z2h);
    cudaGetSymbolAddress((void**)&z2r, g_z2r);
    cudaGetSymbolAddress((void**)&w1f, g_w1f);
    cudaGetSymbolAddress((void**)&w2f, g_w2f);

    cudaFuncSetAttribute(k_gemm_mma, cudaFuncAttributeMaxDynamicSharedMemorySize, SMEM_TOT);

    int mtiles = (NN + 127) / 128;

    // launch order (2 harness pre-launches; ncu -s 5 captures OUR idx 3 = gemm1):
    // 0 init, 1 hist, 2 scan, 3 gemm1 (CSR-independent), 4 fill, 5 agg1, 6 gemm2, 7 agg2
    k_init<<<(NN + 255) / 256, 256>>>(W1l, W1r, W2l, W2r);
    k_hist<<<(NE + 255) / 256, 256>>>(dst);
    k_scan<<<(NN + 1023) / 1024, 1024>>>();
    k_gemm_mma<<<dim3(2, mtiles), 256, SMEM_TOT>>>(x, NN, z1h, 128, z1r, 128, 128, w1f);
    k_fill<<<(NE + 255) / 256, 256>>>(src, dst);
    k_agg1<<<(NN * 32 + 255) / 256, 256>>>(b1);

    k_gemm_mma<<<dim3(1, mtiles), 256, SMEM_TOT>>>(h, NN, z2h, 64, z2r, 64, 64, w2f);
    k_agg2<<<(NN * 32 + 255) / 256, 256>>>(b2, out);
}